// round 16
// baseline (speedup 1.0000x reference)
#include <cuda_runtime.h>
#include <math.h>
#include <stdint.h>

#define B_  2
#define L_  2048
#define D_  1024
#define H_  16
#define HD_ 64
#define DQK 128   // concat head dim [q | q_g]

// ---------------- static scratch (allocation-free rule) ----------------
__device__ float g_qcat[(size_t)B_*H_*L_*DQK];   // tf32-rounded
__device__ float g_kcat[(size_t)B_*H_*L_*DQK];   // tf32-rounded
__device__ float g_v  [(size_t)B_*H_*L_*HD_];    // tf32-rounded
__device__ float g_y  [(size_t)B_*L_*D_];        // tf32-rounded by flash
__device__ float g_xr [(size_t)B_*L_*D_];        // tf32-rounded x
__device__ float g_wqkvT[(size_t)3*D_*D_];       // W_qkv^T, rounded
__device__ float g_woutT[(size_t)D_*D_];         // W_out^T, rounded

// ---------------- helpers ----------------
__device__ __forceinline__ float tf32r(float x){
    uint32_t b; asm("cvt.rna.tf32.f32 %0, %1;" : "=r"(b) : "f"(x));
    return __uint_as_float(b);
}
__device__ __forceinline__ float ex2(float x){
    float y; asm("ex2.approx.ftz.f32 %0, %1;" : "=f"(y) : "f"(x)); return y;
}
__device__ __forceinline__ uint32_t smem_u32(const void* p){
    uint32_t a;
    asm("{ .reg .u64 t; cvta.to.shared.u64 t, %1; cvt.u32.u64 %0, t; }" : "=r"(a) : "l"(p));
    return a;
}
__device__ __forceinline__ void cp16(uint32_t dst, const void* src){
    asm volatile("cp.async.cg.shared.global [%0], [%1], 16;" :: "r"(dst), "l"(src));
}
#define CP_COMMIT() asm volatile("cp.async.commit_group;" ::: "memory")
#define CP_WAIT(n)  asm volatile("cp.async.wait_group %0;" :: "n"(n) : "memory")

// m16n8k8 tf32 MMA: d += a*b, f32 accum.
__device__ __forceinline__ void mma8(float c[4], const uint32_t a[4], const uint32_t b[2]){
    asm volatile(
        "mma.sync.aligned.m16n8k8.row.col.f32.tf32.tf32.f32 "
        "{%0,%1,%2,%3}, {%4,%5,%6,%7}, {%8,%9}, {%0,%1,%2,%3};"
        : "+f"(c[0]), "+f"(c[1]), "+f"(c[2]), "+f"(c[3])
        : "r"(a[0]), "r"(a[1]), "r"(a[2]), "r"(a[3]), "r"(b[0]), "r"(b[1]));
}
// ldmatrix x4: four 8x8 b16 tiles (= four 8row x 16B tiles of tf32)
__device__ __forceinline__ void ldsm4(uint32_t r[4], uint32_t a){
    asm volatile("ldmatrix.sync.aligned.m8n8.x4.shared.b16 {%0,%1,%2,%3}, [%4];"
        : "=r"(r[0]), "=r"(r[1]), "=r"(r[2]), "=r"(r[3]) : "r"(a));
}

// XOR swizzle, 128-float rows: float (r,k) -> r*128 + (k ^ ((r&7)*4))
#define SWZ(r,k)  (((r) << 7) + ((k) ^ (((r) & 7) << 2)))
// V swizzle, 64-float rows: float (r,j) -> r*64 + (j ^ ((r&3)*8))
#define VSWZ(r,j) (((r) << 6) + ((j) ^ (((r) & 3) << 3)))
// P swizzle, 64-float rows, 16B-unit xor keyed on row&7 (ldmatrix conflict-free)
#define PSWZ(r,c) (((r) << 6) + (((((c) >> 2) ^ ((r) & 7)) << 2) | ((c) & 3)))

// ---------------------------------------------------------------------------
// Pre-processing
// ---------------------------------------------------------------------------
__global__ void round_x_kernel(const float* __restrict__ x)
{
    int i = blockIdx.x * blockDim.x + threadIdx.x;
    float4 v = ((const float4*)x)[i];
    v.x = tf32r(v.x); v.y = tf32r(v.y); v.z = tf32r(v.z); v.w = tf32r(v.w);
    ((float4*)g_xr)[i] = v;
}

__global__ void transpose_round_kernel(const float* __restrict__ W,
                                       float* __restrict__ Wt, int Ncols)
{
    __shared__ float t[32][33];
    int bx = blockIdx.x * 32, by = blockIdx.y * 32;
    int tx = threadIdx.x, ty = threadIdx.y;
    #pragma unroll
    for (int i = ty; i < 32; i += 8)
        t[i][tx] = W[(size_t)(by + i) * Ncols + bx + tx];
    __syncthreads();
    #pragma unroll
    for (int i = ty; i < 32; i += 8)
        Wt[(size_t)(bx + i) * 1024 + by + tx] = tf32r(t[tx][i]);
}

__global__ void scatter_g_kernel(const float* __restrict__ qg,
                                 const float* __restrict__ kg)
{
    int i4 = blockIdx.x * blockDim.x + threadIdx.x;
    const int total4 = B_*L_*D_/4;
    if (i4 >= total4) return;
    int flat = i4 * 4;
    int b  = flat / (L_*D_);
    int rem = flat - b*(L_*D_);
    int l  = rem >> 10;
    int dd = rem & 1023;
    int h  = dd >> 6;
    int d  = dd & 63;
    size_t dst = ((size_t)(b*H_ + h)*L_ + l)*DQK + 64 + d;
    float4 a = *(const float4*)&qg[flat];
    float4 c = *(const float4*)&kg[flat];
    a.x=tf32r(a.x); a.y=tf32r(a.y); a.z=tf32r(a.z); a.w=tf32r(a.w);
    c.x=tf32r(c.x); c.y=tf32r(c.y); c.z=tf32r(c.z); c.w=tf32r(c.w);
    *(float4*)&g_qcat[dst] = a;
    *(float4*)&g_kcat[dst] = c;
}

// ---------------------------------------------------------------------------
// tf32 mma.sync GEMM (unchanged from R15): 128x128 tile, 2x4 warps, K-chunk 32,
// 3-stage cp.async ring, ldmatrix fragment feeds, 2 CTAs/SM.
// ---------------------------------------------------------------------------
#define GSTAGE_B 32768
#define GSMEM_BYTES (3*GSTAGE_B)   // 98304

__global__ __launch_bounds__(256, 2) void mm_gemm(float* __restrict__ C, int mode)
{
    extern __shared__ float sm[];
    const uint32_t sb = smem_u32(sm);
    const int tid = threadIdx.x;
    const int lane = tid & 31, wid = tid >> 5;
    const int wy = wid >> 2, wx = wid & 3;
    const int l8 = lane & 7, g = lane >> 3;
    const int bn = blockIdx.x * 128, bm = blockIdx.y * 128;
    const int K = 1024;
    const float* A  = mode ? g_y     : g_xr;
    const float* Bt = mode ? g_woutT : g_wqkvT;

    float acc[4][4][4];
    #pragma unroll
    for (int i = 0; i < 4; i++)
        #pragma unroll
        for (int j = 0; j < 4; j++)
            #pragma unroll
            for (int q = 0; q < 4; q++) acc[i][j][q] = 0.f;

    auto prefetch = [&](int c) {
        const uint32_t base = (uint32_t)(c % 3) * GSTAGE_B;
        #pragma unroll
        for (int t = 0; t < 4; t++) {
            int idx = tid + t * 256;
            int row = idx >> 3, u = idx & 7;
            uint32_t off = (row << 7) + (((u) ^ (row & 7)) << 4);
            cp16(sb + base + off,         &A [(size_t)(bm + row)*K + c*32 + u*4]);
            cp16(sb + base + 16384 + off, &Bt[(size_t)(bn + row)*K + c*32 + u*4]);
        }
        CP_COMMIT();
    };

    const int arow = wy*64 + l8 + ((g & 1) << 3);
    const int adu  = g >> 1;
    const int brow = wx*32 + l8 + ((g >> 1) << 3);
    const int bdu  = g & 1;

    prefetch(0);
    prefetch(1);
    for (int c = 0; c < 32; c++) {
        if (c < 31) { CP_WAIT(1); } else { CP_WAIT(0); }
        __syncthreads();
        if (c + 2 < 32) prefetch(c + 2);

        const uint32_t sA = sb + (uint32_t)(c % 3) * GSTAGE_B;
        const uint32_t sB = sA + 16384;
        #pragma unroll
        for (int ks = 0; ks < 4; ks++) {
            uint32_t a[4][4], bb[2][4];
            #pragma unroll
            for (int mt = 0; mt < 4; mt++) {
                const int r = arow + mt*16;
                ldsm4(a[mt], sA + (r << 7) + ((((2*ks + adu)) ^ l8) << 4));
            }
            #pragma unroll
            for (int p = 0; p < 2; p++) {
                const int r = brow + p*16;
                ldsm4(bb[p], sB + (r << 7) + ((((2*ks + bdu)) ^ l8) << 4));
            }
            #pragma unroll
            for (int mt = 0; mt < 4; mt++)
                #pragma unroll
                for (int p = 0; p < 2; p++) {
                    mma8(acc[mt][2*p + 0], a[mt], &bb[p][0]);
                    mma8(acc[mt][2*p + 1], a[mt], &bb[p][2]);
                }
        }
    }

    #pragma unroll
    for (int mt = 0; mt < 4; mt++) {
        #pragma unroll
        for (int hh = 0; hh < 2; hh++) {
            const int m = bm + wy*64 + mt*16 + (lane >> 2) + hh*8;
            #pragma unroll
            for (int nt = 0; nt < 4; nt++) {
                const int n = bn + wx*32 + nt*8 + 2*(lane & 3);
                float c0 = acc[mt][nt][hh*2 + 0];
                float c1 = acc[mt][nt][hh*2 + 1];
                if (mode == 1) {
                    *(float2*)&C[(size_t)m*1024 + n] = make_float2(c0, c1);
                } else {
                    const int sel = n >> 10;
                    const int h   = (n & 1023) >> 6;
                    const int d   = n & 63;
                    const int b   = m >> 11, l = m & 2047;
                    const size_t bhrow = (size_t)(b*H_ + h)*L_ + l;
                    float2 v = make_float2(tf32r(c0), tf32r(c1));
                    if (sel == 0)      *(float2*)&g_qcat[bhrow*DQK + d] = v;
                    else if (sel == 1) *(float2*)&g_kcat[bhrow*DQK + d] = v;
                    else               *(float2*)&g_v  [bhrow*HD_ + d] = v;
                }
            }
        }
    }
}

// ---------------------------------------------------------------------------
// Flash attention v2 (causal): 64q x 64k tiles, 2 CTAs/SM, tf32 mma.sync,
// no online max, ldmatrix feeds, separate P buffer (K prefetch overlaps
// exp+PV), co-resident CTA hides barriers / exp / V latency.
// smem floats: sQ[0,8192) sK[8192,16384) sP[16384,20480) sV[20480,24576)
//              psum[24576,24832) rowl[24832,24896)  => 99584 B
// ---------------------------------------------------------------------------
#define OFQ  0
#define OFK  8192
#define OFP  16384
#define OFV  20480
#define OFPS 24576
#define OFRL 24832
#define FSMEM_BYTES (24896*4)   // 99584

__global__ __launch_bounds__(256, 2) void flash_kernel()
{
    extern __shared__ float sm[];
    const uint32_t sb = smem_u32(sm);
    float* sP   = sm + OFP;
    float* sV   = sm + OFV;
    float* psum = sm + OFPS;
    float* rowl = sm + OFRL;

    const int qb  = gridDim.x - 1 - blockIdx.x;   // 0..31, heavy blocks first
    const int bh  = blockIdx.y;
    const int tid = threadIdx.x;
    const int lane = tid & 31, wid = tid >> 5;
    const int wy = wid >> 2, wx = wid & 3;        // 2(m) x 4(n) warp grid
    const int l8 = lane & 7, g = lane >> 3;
    // fold softmax scale AND log2(e) into Q so exp(x) == ex2(prescaled score)
    const float SCALE = 0.125f / logf(2048.0f) * 1.4426950408889634f;

    const float* Qg = g_qcat + (size_t)bh*L_*DQK + (size_t)qb*64*DQK;
    const float* Kg = g_kcat + (size_t)bh*L_*DQK;
    const float* Vg = g_v    + (size_t)bh*L_*HD_;

    // prologue: cp.async K_0 (64x128: 8 float4/thread)
    #pragma unroll
    for (int t = 0; t < 8; t++) {
        int idx = tid + t*256;
        int r = idx >> 5, jw = (idx & 31)*4;
        cp16(sb + 4*(OFK + SWZ(r, jw)), &Kg[r*128 + jw]);
    }
    CP_COMMIT();

    // Q load + prescale (64x128)
    #pragma unroll
    for (int t = 0; t < 8; t++) {
        int i = tid + t*256;
        int r = i >> 5, j4 = (i & 31)*4;
        float4 v = *(const float4*)&Qg[r*128 + j4];
        v.x = tf32r(v.x*SCALE); v.y = tf32r(v.y*SCALE);
        v.z = tf32r(v.z*SCALE); v.w = tf32r(v.w*SCALE);
        *(float4*)&sm[SWZ(r, j4)] = v;
    }

    // ldmatrix lane addressing
    const int arow = wy*32 + l8 + ((g & 1) << 3);   // A rows (+mt*16)
    const int adu  = g >> 1;
    const int brow = wx*16 + l8 + ((g >> 1) << 3);  // B rows (warp's 16 keys)
    const int bdu  = g & 1;

    float o[2][2][4], rs_acc[2][2];
    #pragma unroll
    for (int i = 0; i < 2; i++) {
        rs_acc[i][0] = 0.f; rs_acc[i][1] = 0.f;
        #pragma unroll
        for (int j = 0; j < 2; j++)
            #pragma unroll
            for (int q = 0; q < 4; q++) o[i][j][q] = 0.f;
    }

    for (int kt = 0; kt <= qb; kt++) {
        // 1. close PV_{kt-1} (sV, sP free); kt=0: Q stores done
        __syncthreads();

        // 2. issue V_kt (64x64: 4 float4/thread)
        #pragma unroll
        for (int t = 0; t < 4; t++) {
            int idx = tid + t*256;
            int r = idx >> 4, j = (idx & 15)*4;
            cp16(sb + 4*(OFV + VSWZ(r, j)), &Vg[(size_t)(kt*64 + r)*64 + j]);
        }
        CP_COMMIT();
        CP_WAIT(0);            // K_kt (prefetched last iter) + V_kt complete
        __syncthreads();       // visible to all warps

        // 3. S = Q @ K^T (16 ks over d=128)
        float s[2][2][4];
        #pragma unroll
        for (int i = 0; i < 2; i++)
            #pragma unroll
            for (int j = 0; j < 2; j++)
                #pragma unroll
                for (int q = 0; q < 4; q++) s[i][j][q] = 0.f;

        #pragma unroll
        for (int ks = 0; ks < 16; ks++) {
            uint32_t a[2][4], bb[4];
            ldsm4(a[0], sb + ((uint32_t)(arow)      << 9) + (((2*ks + adu) ^ l8) << 4));
            ldsm4(a[1], sb + ((uint32_t)(arow + 16) << 9) + (((2*ks + adu) ^ l8) << 4));
            ldsm4(bb,   sb + 4*OFK + ((uint32_t)brow << 9) + (((2*ks + bdu) ^ l8) << 4));
            mma8(s[0][0], a[0], &bb[0]); mma8(s[0][1], a[0], &bb[2]);
            mma8(s[1][0], a[1], &bb[0]); mma8(s[1][1], a[1], &bb[2]);
        }
        __syncthreads();       // sK free for prefetch

        // 4. prefetch K_{kt+1} (overlaps exp + PV)
        if (kt < qb) {
            const float* Kn = &Kg[(size_t)(kt + 1)*64*128];
            #pragma unroll
            for (int t = 0; t < 8; t++) {
                int idx = tid + t*256;
                int r = idx >> 5, jw = (idx & 31)*4;
                cp16(sb + 4*(OFK + SWZ(r, jw)), &Kn[r*128 + jw]);
            }
            CP_COMMIT();
        }

        // 5. exp (no max shift), P -> sP
        const bool diag = (kt == qb);
        #pragma unroll
        for (int mt = 0; mt < 2; mt++) {
            #pragma unroll
            for (int hh = 0; hh < 2; hh++) {
                const int rloc = wy*32 + mt*16 + (lane >> 2) + hh*8;
                float rs = 0.f;
                #pragma unroll
                for (int nt = 0; nt < 2; nt++) {
                    const int cloc = wx*16 + nt*8 + 2*(lane & 3);
                    float v0 = s[mt][nt][hh*2 + 0];
                    float v1 = s[mt][nt][hh*2 + 1];
                    if (diag) {
                        if (cloc + 0 > rloc) v0 = -1e30f;
                        if (cloc + 1 > rloc) v1 = -1e30f;
                    }
                    float p0 = ex2(v0);
                    float p1 = ex2(v1);
                    rs += p0 + p1;
                    *(float2*)&sP[PSWZ(rloc, cloc)] = make_float2(tf32r(p0), tf32r(p1));
                }
                rs_acc[mt][hh] += rs;
            }
        }
        __syncthreads();       // P visible

        // 6. O += P @ V (8 ks over 64 keys; P via ldmatrix, V scalar)
        #pragma unroll
        for (int ks = 0; ks < 8; ks++) {
            const int kc = ks*8 + (lane & 3);
            uint32_t a[2][4], b[2][2];
            ldsm4(a[0], sb + 4*OFP + ((uint32_t)(arow)      << 8) + (((2*ks + adu) ^ l8) << 4));
            ldsm4(a[1], sb + 4*OFP + ((uint32_t)(arow + 16) << 8) + (((2*ks + adu) ^ l8) << 4));
            #pragma unroll
            for (int nt = 0; nt < 2; nt++) {
                const int col = wx*16 + nt*8 + (lane >> 2);
                b[nt][0] = __float_as_uint(sV[VSWZ(kc,     col)]);
                b[nt][1] = __float_as_uint(sV[VSWZ(kc + 4, col)]);
            }
            mma8(o[0][0], a[0], b[0]); mma8(o[0][1], a[0], b[1]);
            mma8(o[1][0], a[1], b[0]); mma8(o[1][1], a[1], b[1]);
        }
    }

    // ---- single rowsum reduction (64 rows) ----
    #pragma unroll
    for (int mt = 0; mt < 2; mt++) {
        #pragma unroll
        for (int hh = 0; hh < 2; hh++) {
            float rs = rs_acc[mt][hh];
            rs += __shfl_xor_sync(0xffffffffu, rs, 1);
            rs += __shfl_xor_sync(0xffffffffu, rs, 2);
            const int rloc = wy*32 + mt*16 + (lane >> 2) + hh*8;
            if ((lane & 3) == 0) psum[rloc*4 + wx] = rs;
        }
    }
    __syncthreads();
    if (tid < 64)
        rowl[tid] = psum[tid*4+0] + psum[tid*4+1] + psum[tid*4+2] + psum[tid*4+3];
    __syncthreads();

    // epilogue: normalize, tf32-round, write g_y [B,L,D]
    const int b = bh >> 4, h = bh & 15;
    #pragma unroll
    for (int mt = 0; mt < 2; mt++) {
        #pragma unroll
        for (int hh = 0; hh < 2; hh++) {
            const int rloc = wy*32 + mt*16 + (lane >> 2) + hh*8;
            const float inv = 1.f / rowl[rloc];
            const int qrow = qb*64 + rloc;
            #pragma unroll
            for (int nt = 0; nt < 2; nt++) {
                const int col = h*64 + wx*16 + nt*8 + 2*(lane & 3);
                float2 v = make_float2(tf32r(o[mt][nt][hh*2+0]*inv),
                                       tf32r(o[mt][nt][hh*2+1]*inv));
                *(float2*)&g_y[((size_t)b*L_ + qrow)*D_ + col] = v;
            }
        }
    }
}

// ---------------------------------------------------------------------------
extern "C" void kernel_launch(void* const* d_in, const int* in_sizes, int n_in,
                              void* d_out, int out_size)
{
    const float* x    = (const float*)d_in[0];
    const float* qg   = (const float*)d_in[1];
    const float* kg   = (const float*)d_in[2];
    const float* Wqkv = (const float*)d_in[3];
    const float* Wout = (const float*)d_in[4];
    float* out = (float*)d_out;

    cudaFuncSetAttribute(flash_kernel,
                         cudaFuncAttributeMaxDynamicSharedMemorySize, FSMEM_BYTES);
    cudaFuncSetAttribute(mm_gemm,
                         cudaFuncAttributeMaxDynamicSharedMemorySize, GSMEM_BYTES);

    // device addresses of __device__ symbols (host-side symbol use is invalid!)
    float* wqkvT = nullptr; cudaGetSymbolAddress((void**)&wqkvT, g_wqkvT);
    float* woutT = nullptr; cudaGetSymbolAddress((void**)&woutT, g_woutT);

    round_x_kernel<<<B_*L_*D_/4/256, 256>>>(x);
    transpose_round_kernel<<<dim3(3*D_/32, D_/32), dim3(32, 8)>>>(Wqkv, wqkvT, 3*D_);
    transpose_round_kernel<<<dim3(D_/32,   D_/32), dim3(32, 8)>>>(Wout, woutT, D_);

    mm_gemm<<<dim3(3*D_/128, B_*L_/128), 256, GSMEM_BYTES>>>(nullptr, 0);
    scatter_g_kernel<<<(B_*L_*D_/4 + 255)/256, 256>>>(qg, kg);
    flash_kernel<<<dim3(L_/64, B_*H_), 256, FSMEM_BYTES>>>();
    mm_gemm<<<dim3(D_/128, B_*L_/128), 256, GSMEM_BYTES>>>(out, 1);
}